// round 3
// baseline (speedup 1.0000x reference)
#include <cuda_runtime.h>

// DeltaNet chunkwise delta rule.
// Shapes fixed by the problem: b=4, h=4, L=4096, dk=dv=256, chunk=32.

#define LSEQ  4096
#define DKV   256
#define CCH   32
#define NCH   (LSEQ / CCH)      // 128 chunks
#define BHT   16                // b*h
#define JBW   32                // dv block width in phase 2
#define NJB   (DKV / JBW)       // 8 column blocks

#define OUT_ELEMS   ((size_t)BHT * LSEQ * DKV)        // 16777216
#define STATE_ELEMS ((size_t)BHT * DKV * DKV)         // 1048576

// Scratch (device globals; no allocation allowed)
__device__ float g_qn [(size_t)BHT * LSEQ * DKV];
__device__ float g_kn [(size_t)BHT * LSEQ * DKV];
__device__ float g_w  [(size_t)BHT * LSEQ * DKV];
__device__ float g_u  [(size_t)BHT * LSEQ * DKV];
__device__ float g_att[(size_t)BHT * NCH * CCH * CCH];

// ---- packed f32x2 helpers (2x FFMA throughput vs 3-reg FFMA on sm_103a) ----
__device__ __forceinline__ unsigned long long ffma2(unsigned long long a,
                                                    unsigned long long b,
                                                    unsigned long long c) {
    unsigned long long d;
    asm("fma.rn.f32x2 %0, %1, %2, %3;" : "=l"(d) : "l"(a), "l"(b), "l"(c));
    return d;
}
__device__ __forceinline__ unsigned long long splat2(float x) {
    unsigned long long d;
    unsigned int r = __float_as_uint(x);
    asm("mov.b64 %0, {%1, %1};" : "=l"(d) : "r"(r));
    return d;
}
__device__ __forceinline__ float fold2(unsigned long long a) {
    unsigned int lo, hi;
    asm("mov.b64 {%0, %1}, %2;" : "=r"(lo), "=r"(hi) : "l"(a));
    return __uint_as_float(lo) + __uint_as_float(hi);
}

// ============================================================================
// Phase 1: per-chunk preprocessing (parallel over bh * chunks = 2048 CTAs)
//   qn = l2norm(q); kn = l2norm(k); vb = v*beta; kb = kn*beta
//   A  = strict_tril(kb @ kn^T)
//   u  = (I+A)^-1 vb   (forward substitution)
//   w  = (I+A)^-1 kb
//   att = tril(qn @ kn^T)  (incl. diag, zeros above)
// Shared tiles use row stride 260 floats to avoid 256-stride bank pathologies.
// ============================================================================
#define P1_STRIDE 260

__global__ __launch_bounds__(256, 1)
void phase1(const float* __restrict__ q, const float* __restrict__ k,
            const float* __restrict__ v, const float* __restrict__ beta)
{
    const int ch = blockIdx.x;
    const int bh = blockIdx.y;
    extern __shared__ float sm[];
    float* Q   = sm;                         // 32 * 260
    float* K   = Q + 32 * P1_STRIDE;
    float* V   = K + 32 * P1_STRIDE;
    float* W   = V + 32 * P1_STRIDE;
    float* A   = W + 32 * P1_STRIDE;         // 32 * 36
    float* RED = A + 32 * 36;                // 512
    float* BET = RED + 512;                  // 32
    float* NRM = BET + 32;                   // 64

    const int t = threadIdx.x;
    const size_t base = ((size_t)bh * LSEQ + (size_t)ch * CCH) * DKV;
    const float4* q4 = (const float4*)(q + base);
    const float4* k4 = (const float4*)(k + base);
    const float4* v4 = (const float4*)(v + base);

    // load tiles (2048 float4 each, 8 per thread)
#pragma unroll
    for (int r = 0; r < 8; r++) {
        int f   = t + r * 256;
        int row = f >> 6, c4 = f & 63;
        *(float4*)&Q[row * P1_STRIDE + c4 * 4] = q4[f];
        *(float4*)&K[row * P1_STRIDE + c4 * 4] = k4[f];
        *(float4*)&V[row * P1_STRIDE + c4 * 4] = v4[f];
    }
    if (t < CCH) BET[t] = beta[(size_t)bh * LSEQ + ch * CCH + t];
    __syncthreads();

    // row sum-of-squares for q and k
    {
        int r = t >> 3, s = t & 7;
        float aq = 0.f, ak = 0.f;
#pragma unroll
        for (int m = 0; m < 32; m++) {
            float xq = Q[r * P1_STRIDE + s * 32 + m];
            float xk = K[r * P1_STRIDE + s * 32 + m];
            aq += xq * xq;
            ak += xk * xk;
        }
        RED[r * 8 + s]       = aq;
        RED[256 + r * 8 + s] = ak;
    }
    __syncthreads();
    if (t < 64) {
        int r = t & 31, wsel = t >> 5;
        float ssum = 0.f;
#pragma unroll
        for (int s = 0; s < 8; s++) ssum += RED[wsel * 256 + r * 8 + s];
        NRM[t] = rsqrtf(ssum);
    }
    __syncthreads();

    // normalize q,k ; v *= beta ; W = kn * beta
#pragma unroll
    for (int r = 0; r < 8; r++) {
        int f   = t + r * 256;
        int row = f >> 6, c4 = f & 63;
        float nq = NRM[row], nk = NRM[32 + row], be = BET[row];
        float4 xq = *(float4*)&Q[row * P1_STRIDE + c4 * 4];
        xq.x *= nq; xq.y *= nq; xq.z *= nq; xq.w *= nq;
        *(float4*)&Q[row * P1_STRIDE + c4 * 4] = xq;
        float4 xk = *(float4*)&K[row * P1_STRIDE + c4 * 4];
        xk.x *= nk; xk.y *= nk; xk.z *= nk; xk.w *= nk;
        *(float4*)&K[row * P1_STRIDE + c4 * 4] = xk;
        float4 xv = *(float4*)&V[row * P1_STRIDE + c4 * 4];
        xv.x *= be; xv.y *= be; xv.z *= be; xv.w *= be;
        *(float4*)&V[row * P1_STRIDE + c4 * 4] = xv;
        float4 xw;
        xw.x = xk.x * be; xw.y = xk.y * be; xw.z = xk.z * be; xw.w = xk.w * be;
        *(float4*)&W[row * P1_STRIDE + c4 * 4] = xw;
    }
    __syncthreads();

    // A (strict lower, beta_i * kn_i . kn_j) and att (tril incl diag, qn_i . kn_j)
    float* attg = g_att + ((size_t)(bh * NCH + ch)) * (CCH * CCH);
#pragma unroll
    for (int pp = 0; pp < 4; pp++) {
        int p = t + pp * 256;
        int i = p >> 5, j = p & 31;
        float dkk = 0.f, dqk = 0.f;
#pragma unroll 8
        for (int d4 = 0; d4 < 64; d4++) {
            float4 ki = *(float4*)&K[i * P1_STRIDE + d4 * 4];
            float4 kj = *(float4*)&K[j * P1_STRIDE + d4 * 4];
            float4 qi = *(float4*)&Q[i * P1_STRIDE + d4 * 4];
            dkk += ki.x * kj.x + ki.y * kj.y + ki.z * kj.z + ki.w * kj.w;
            dqk += qi.x * kj.x + qi.y * kj.y + qi.z * kj.z + qi.w * kj.w;
        }
        A[i * 36 + j]     = (j < i) ? BET[i] * dkk : 0.f;
        attg[i * 32 + j]  = (j <= i) ? dqk : 0.f;
    }
    __syncthreads();

    // forward substitution: (I+A) u = vb  and  (I+A) w = kb, in place.
    // thread t owns column t of both W (dk) and V (dv).
    for (int i = 1; i < CCH; i++) {
        float accw = W[i * P1_STRIDE + t];
        float accv = V[i * P1_STRIDE + t];
        for (int j = 0; j < i; j++) {
            float a = A[i * 36 + j];
            accw -= a * W[j * P1_STRIDE + t];
            accv -= a * V[j * P1_STRIDE + t];
        }
        W[i * P1_STRIDE + t] = accw;
        V[i * P1_STRIDE + t] = accv;
        __syncthreads();
    }

    // write qn, kn, w, u
    float4* oq = (float4*)(g_qn + base);
    float4* ok = (float4*)(g_kn + base);
    float4* ow = (float4*)(g_w + base);
    float4* ou = (float4*)(g_u + base);
#pragma unroll
    for (int r = 0; r < 8; r++) {
        int f   = t + r * 256;
        int row = f >> 6, c4 = f & 63;
        oq[f] = *(float4*)&Q[row * P1_STRIDE + c4 * 4];
        ok[f] = *(float4*)&K[row * P1_STRIDE + c4 * 4];
        ow[f] = *(float4*)&W[row * P1_STRIDE + c4 * 4];
        ou[f] = *(float4*)&V[row * P1_STRIDE + c4 * 4];
    }
}

// ============================================================================
// Phase 2: sequential scan over chunks. Grid = (NJB, BHT) = 128 CTAs.
// Each CTA owns S slice [256 dk x 32 dv], kept in smem as St[j][d] (transposed)
// with a 16B-granularity XOR swizzle keyed by (j>>1)&7 for conflict freedom.
// ============================================================================
#define P2_STRIDE 260   // W/Q/K tile row stride (floats)

__global__ __launch_bounds__(256, 1)
void phase2(float* __restrict__ out, int write_state)
{
    const int jb = blockIdx.x;
    const int bh = blockIdx.y;
    extern __shared__ float sm[];
    float* Wt   = sm;                          // 32 * 260
    float* Qt   = Wt + 32 * P2_STRIDE;
    float* Kt   = Qt + 32 * P2_STRIDE;
    float* St   = Kt + 32 * P2_STRIDE;         // 32 * 256 (S^T, swizzled)
    float* Usl  = St + 32 * 256;               // 32 * 36
    float* ATTs = Usl + 32 * 36;
    float* WS   = ATTs + 32 * 36;
    float* QS   = WS + 32 * 36;
    float* UADJ = QS + 32 * 36;

    const int t = threadIdx.x;

    // zero S
#pragma unroll
    for (int r = 0; r < 32; r++) St[t + r * 256] = 0.f;
    __syncthreads();

    // GEMM-A thread map: 2x2 output tile (i-pair, j-pair)
    const int ip = t >> 4, jp = t & 15;
    const int i0 = 2 * ip, i1 = 2 * ip + 1;
    const int j0 = 2 * jp, j1 = 2 * jp + 1;
    const int keyA = jp & 7;                   // == (j0>>1)&7 == (j1>>1)&7
    // GEMM-C thread map: thread owns (row j of S^T, d-block dg)
    const int jj = t & 31, dg = t >> 5;
    const int keyC = (jj >> 1) & 7;

    for (int ch = 0; ch < NCH; ch++) {
        // ---- load chunk tiles ----
        {
            const size_t base = ((size_t)bh * LSEQ + (size_t)ch * CCH) * DKV;
            const float4* w4 = (const float4*)(g_w + base);
            const float4* q4 = (const float4*)(g_qn + base);
            const float4* k4 = (const float4*)(g_kn + base);
#pragma unroll
            for (int r = 0; r < 8; r++) {
                int f   = t + r * 256;
                int row = f >> 6, c4 = f & 63;
                *(float4*)&Wt[row * P2_STRIDE + c4 * 4] = w4[f];
                *(float4*)&Qt[row * P2_STRIDE + c4 * 4] = q4[f];
                *(float4*)&Kt[row * P2_STRIDE + c4 * 4] = k4[f];
            }
            int i = t >> 3, jq = t & 7;
            *(float4*)&Usl[i * 36 + jq * 4] =
                *(const float4*)&g_u[base + (size_t)i * DKV + jb * JBW + jq * 4];
            *(float4*)&ATTs[i * 36 + jq * 4] =
                *(const float4*)&g_att[((size_t)(bh * NCH + ch)) * 1024 + i * 32 + jq * 4];
        }
        __syncthreads();

        // ---- GEMM A: WS = w @ S, QS = q @ S  (f32x2, d-vectorized) ----
        {
            unsigned long long w00 = 0, w01 = 0, w10 = 0, w11 = 0;
            unsigned long long p00 = 0, p01 = 0, p10 = 0, p11 = 0;
            const ulonglong2* wr0 = (const ulonglong2*)&Wt[i0 * P2_STRIDE];
            const ulonglong2* wr1 = (const ulonglong2*)&Wt[i1 * P2_STRIDE];
            const ulonglong2* qr0 = (const ulonglong2*)&Qt[i0 * P2_STRIDE];
            const ulonglong2* qr1 = (const ulonglong2*)&Qt[i1 * P2_STRIDE];
            const float* sr0 = &St[j0 * 256];
            const float* sr1 = &St[j1 * 256];
#pragma unroll 4
            for (int d4 = 0; d4 < 64; d4++) {
                int u = d4 ^ keyA;
                ulonglong2 sv0 = *(const ulonglong2*)&sr0[u << 2];
                ulonglong2 sv1 = *(const ulonglong2*)&sr1[u << 2];
                ulonglong2 wv0 = wr0[d4];
                ulonglong2 wv1 = wr1[d4];
                ulonglong2 qv0 = qr0[d4];
                ulonglong2 qv1 = qr1[d4];
                w00 = ffma2(wv0.x, sv0.x, w00); w00 = ffma2(wv0.y, sv0.y, w00);
                w01 = ffma2(wv0.x, sv1.x, w01); w01 = ffma2(wv0.y, sv1.y, w01);
                w10 = ffma2(wv1.x, sv0.x, w10); w10 = ffma2(wv1.y, sv0.y, w10);
                w11 = ffma2(wv1.x, sv1.x, w11); w11 = ffma2(wv1.y, sv1.y, w11);
                p00 = ffma2(qv0.x, sv0.x, p00); p00 = ffma2(qv0.y, sv0.y, p00);
                p01 = ffma2(qv0.x, sv1.x, p01); p01 = ffma2(qv0.y, sv1.y, p01);
                p10 = ffma2(qv1.x, sv0.x, p10); p10 = ffma2(qv1.y, sv0.y, p10);
                p11 = ffma2(qv1.x, sv1.x, p11); p11 = ffma2(qv1.y, sv1.y, p11);
            }
            WS[i0 * 36 + j0] = fold2(w00);
            WS[i0 * 36 + j1] = fold2(w01);
            WS[i1 * 36 + j0] = fold2(w10);
            WS[i1 * 36 + j1] = fold2(w11);
            QS[i0 * 36 + j0] = fold2(p00);
            QS[i0 * 36 + j1] = fold2(p01);
            QS[i1 * 36 + j0] = fold2(p10);
            QS[i1 * 36 + j1] = fold2(p11);
        }
        __syncthreads();

        // ---- UADJ = u - WS ----
        {
            int i = t >> 3, jq = t & 7;
            float4 uu = *(float4*)&Usl[i * 36 + jq * 4];
            float4 ww = *(float4*)&WS[i * 36 + jq * 4];
            float4 r;
            r.x = uu.x - ww.x; r.y = uu.y - ww.y;
            r.z = uu.z - ww.z; r.w = uu.w - ww.w;
            *(float4*)&UADJ[i * 36 + jq * 4] = r;
        }
        __syncthreads();

        // ---- O = QS + att @ UADJ ; write to global ----
        {
            int i = t >> 3, jq = t & 7;
            float4 o = *(float4*)&QS[i * 36 + jq * 4];
#pragma unroll 8
            for (int ii = 0; ii < CCH; ii++) {
                float a = ATTs[i * 36 + ii];   // zero above diag
                float4 ub = *(float4*)&UADJ[ii * 36 + jq * 4];
                o.x += a * ub.x; o.y += a * ub.y;
                o.z += a * ub.z; o.w += a * ub.w;
            }
            *(float4*)&out[((size_t)bh * LSEQ + (size_t)ch * CCH + i) * DKV +
                           jb * JBW + jq * 4] = o;
        }

        // ---- GEMM C: S += k^T @ UADJ  (register-resident RMW of own St block) ----
        {
            ulonglong2 sa[8];
            float* srow = &St[jj * 256];
#pragma unroll
            for (int m = 0; m < 8; m++) {
                int u = (dg * 8 + m) ^ keyC;
                sa[m] = *(const ulonglong2*)&srow[u << 2];
            }
#pragma unroll 4
            for (int i = 0; i < CCH; i++) {
                unsigned long long us = splat2(UADJ[i * 36 + jj]);
                const ulonglong2* kr = (const ulonglong2*)&Kt[i * P2_STRIDE + dg * 32];
#pragma unroll
                for (int m = 0; m < 8; m++) {
                    ulonglong2 kv = kr[m];
                    sa[m].x = ffma2(kv.x, us, sa[m].x);
                    sa[m].y = ffma2(kv.y, us, sa[m].y);
                }
            }
#pragma unroll
            for (int m = 0; m < 8; m++) {
                int u = (dg * 8 + m) ^ keyC;
                *(ulonglong2*)&srow[u << 2] = sa[m];
            }
        }
        __syncthreads();
    }

    // ---- final state S (second tuple element) ----
    if (write_state) {
        const size_t soff = OUT_ELEMS;
#pragma unroll 4
        for (int m = 0; m < 32; m++) {
            int d = dg * 32 + m;
            int u = (dg * 8 + (m >> 2)) ^ keyC;
            float val = St[jj * 256 + (u << 2) + (m & 3)];
            out[soff + ((size_t)bh * DKV + d) * DKV + jb * JBW + jj] = val;
        }
    }
}

// ============================================================================

#define SM1_BYTES ((32 * P1_STRIDE * 4 + 32 * 36 + 512 + 32 + 64) * sizeof(float))
#define SM2_BYTES ((32 * P2_STRIDE * 3 + 32 * 256 + 5 * 32 * 36) * sizeof(float))

extern "C" void kernel_launch(void* const* d_in, const int* in_sizes, int n_in,
                              void* d_out, int out_size)
{
    const float* q    = (const float*)d_in[0];
    const float* k    = (const float*)d_in[1];
    const float* v    = (const float*)d_in[2];
    const float* beta = (const float*)d_in[3];
    float* out = (float*)d_out;

    cudaFuncSetAttribute(phase1, cudaFuncAttributeMaxDynamicSharedMemorySize, SM1_BYTES);
    cudaFuncSetAttribute(phase2, cudaFuncAttributeMaxDynamicSharedMemorySize, SM2_BYTES);

    phase1<<<dim3(NCH, BHT), 256, SM1_BYTES>>>(q, k, v, beta);

    int ws = ((size_t)out_size >= OUT_ELEMS + STATE_ELEMS) ? 1 : 0;
    phase2<<<dim3(NJB, BHT), 256, SM2_BYTES>>>(out, ws);
}

// round 6
// speedup vs baseline: 1.0914x; 1.0914x over previous
#include <cuda_runtime.h>

// DeltaNet chunkwise delta rule.
// Shapes fixed by the problem: b=4, h=4, L=4096, dk=dv=256, chunk=32.

#define LSEQ  4096
#define DKV   256
#define CCH   32
#define NCH   (LSEQ / CCH)      // 128 chunks
#define BHT   16                // b*h
#define JBW   32                // dv block width in phase 2
#define NJB   (DKV / JBW)       // 8 column blocks

#define OUT_ELEMS   ((size_t)BHT * LSEQ * DKV)        // 16777216
#define STATE_ELEMS ((size_t)BHT * DKV * DKV)         // 1048576

// Scratch (device globals; no allocation allowed)
__device__ float g_qn [(size_t)BHT * LSEQ * DKV];
__device__ float g_kn [(size_t)BHT * LSEQ * DKV];
__device__ float g_w  [(size_t)BHT * LSEQ * DKV];
__device__ float g_u  [(size_t)BHT * LSEQ * DKV];
__device__ float g_att[(size_t)BHT * NCH * CCH * CCH];

// ---- packed f32x2 helpers (2x FFMA throughput vs 3-reg FFMA on sm_103a) ----
__device__ __forceinline__ unsigned long long ffma2(unsigned long long a,
                                                    unsigned long long b,
                                                    unsigned long long c) {
    unsigned long long d;
    asm("fma.rn.f32x2 %0, %1, %2, %3;" : "=l"(d) : "l"(a), "l"(b), "l"(c));
    return d;
}
__device__ __forceinline__ unsigned long long splat2(float x) {
    unsigned long long d;
    unsigned int r = __float_as_uint(x);
    asm("mov.b64 %0, {%1, %1};" : "=l"(d) : "r"(r));
    return d;
}
__device__ __forceinline__ float fold2(unsigned long long a) {
    unsigned int lo, hi;
    asm("mov.b64 {%0, %1}, %2;" : "=r"(lo), "=r"(hi) : "l"(a));
    return __uint_as_float(lo) + __uint_as_float(hi);
}

// ============================================================================
// Phase 1: per-chunk preprocessing (parallel over bh * chunks = 2048 CTAs).
// 3 smem tiles only (Q,K,V) -> 107KB -> 2 CTAs/SM for latency hiding.
//   qn = l2norm(q); kn = l2norm(k); vb = v*beta
//   A  = strict_tril(beta_i * kn_i . kn_j)
//   w  = (I+A)^-1 (kn*beta)   in-place on K tile (beta folded into row init)
//   u  = (I+A)^-1 vb          in-place on V tile
//   att = tril(qn @ kn^T)
// ============================================================================
#define P1S 260

__global__ __launch_bounds__(256, 2)
void phase1(const float* __restrict__ q, const float* __restrict__ k,
            const float* __restrict__ v, const float* __restrict__ beta)
{
    const int ch = blockIdx.x;
    const int bh = blockIdx.y;
    extern __shared__ float sm[];
    float* Q   = sm;                         // 32 * 260
    float* K   = Q + 32 * P1S;
    float* V   = K + 32 * P1S;
    float* A   = V + 32 * P1S;               // 32 * 36
    float* RED = A + 32 * 36;                // 512
    float* BET = RED + 512;                  // 32
    float* NRM = BET + 32;                   // 64

    const int t = threadIdx.x;
    const size_t base = ((size_t)bh * LSEQ + (size_t)ch * CCH) * DKV;
    const float4* q4 = (const float4*)(q + base);
    const float4* k4 = (const float4*)(k + base);
    const float4* v4 = (const float4*)(v + base);

    // load tiles (2048 float4 each, 8 per thread)
#pragma unroll
    for (int r = 0; r < 8; r++) {
        int f   = t + r * 256;
        int row = f >> 6, c4 = f & 63;
        *(float4*)&Q[row * P1S + c4 * 4] = q4[f];
        *(float4*)&K[row * P1S + c4 * 4] = k4[f];
        *(float4*)&V[row * P1S + c4 * 4] = v4[f];
    }
    if (t < CCH) BET[t] = beta[(size_t)bh * LSEQ + ch * CCH + t];
    __syncthreads();

    // row sum-of-squares for q and k
    {
        int r = t >> 3, s = t & 7;
        float aq = 0.f, ak = 0.f;
#pragma unroll
        for (int m = 0; m < 32; m++) {
            float xq = Q[r * P1S + s * 32 + m];
            float xk = K[r * P1S + s * 32 + m];
            aq += xq * xq;
            ak += xk * xk;
        }
        RED[r * 8 + s]       = aq;
        RED[256 + r * 8 + s] = ak;
    }
    __syncthreads();
    if (t < 64) {
        int r = t & 31, wsel = t >> 5;
        float ssum = 0.f;
#pragma unroll
        for (int s = 0; s < 8; s++) ssum += RED[wsel * 256 + r * 8 + s];
        NRM[t] = rsqrtf(ssum);
    }
    __syncthreads();

    // normalize q,k (write qn,kn straight to global) ; v *= beta
    {
        float4* oq = (float4*)(g_qn + base);
        float4* ok = (float4*)(g_kn + base);
#pragma unroll
        for (int r = 0; r < 8; r++) {
            int f   = t + r * 256;
            int row = f >> 6, c4 = f & 63;
            float nq = NRM[row], nk = NRM[32 + row], be = BET[row];
            float4 xq = *(float4*)&Q[row * P1S + c4 * 4];
            xq.x *= nq; xq.y *= nq; xq.z *= nq; xq.w *= nq;
            *(float4*)&Q[row * P1S + c4 * 4] = xq;
            oq[f] = xq;
            float4 xk = *(float4*)&K[row * P1S + c4 * 4];
            xk.x *= nk; xk.y *= nk; xk.z *= nk; xk.w *= nk;
            *(float4*)&K[row * P1S + c4 * 4] = xk;
            ok[f] = xk;
            float4 xv = *(float4*)&V[row * P1S + c4 * 4];
            xv.x *= be; xv.y *= be; xv.z *= be; xv.w *= be;
            *(float4*)&V[row * P1S + c4 * 4] = xv;
        }
    }
    __syncthreads();

    // A (strict lower, beta_i * kn_i . kn_j) and att (tril incl diag)
    float* attg = g_att + ((size_t)(bh * NCH + ch)) * (CCH * CCH);
#pragma unroll
    for (int pp = 0; pp < 4; pp++) {
        int p = t + pp * 256;
        int i = p >> 5, j = p & 31;
        float dkk = 0.f, dqk = 0.f;
#pragma unroll 8
        for (int d4 = 0; d4 < 64; d4++) {
            float4 ki = *(float4*)&K[i * P1S + d4 * 4];
            float4 kj = *(float4*)&K[j * P1S + d4 * 4];
            float4 qi = *(float4*)&Q[i * P1S + d4 * 4];
            dkk += ki.x * kj.x + ki.y * kj.y + ki.z * kj.z + ki.w * kj.w;
            dqk += qi.x * kj.x + qi.y * kj.y + qi.z * kj.z + qi.w * kj.w;
        }
        A[i * 36 + j]     = (j < i) ? BET[i] * dkk : 0.f;
        attg[i * 32 + j]  = (j <= i) ? dqk : 0.f;
    }
    __syncthreads();

    // forward substitution in place: K row i starts at beta_i*kn_i -> w,
    // V row i starts at beta_i*v_i -> u. Thread t owns column t of both.
    for (int i = 0; i < CCH; i++) {
        float accw = BET[i] * K[i * P1S + t];
        float accv = V[i * P1S + t];
        for (int j = 0; j < i; j++) {
            float a = A[i * 36 + j];
            accw -= a * K[j * P1S + t];
            accv -= a * V[j * P1S + t];
        }
        K[i * P1S + t] = accw;
        V[i * P1S + t] = accv;
        __syncthreads();
    }

    // write w, u
    {
        float4* ow = (float4*)(g_w + base);
        float4* ou = (float4*)(g_u + base);
#pragma unroll
        for (int r = 0; r < 8; r++) {
            int f   = t + r * 256;
            int row = f >> 6, c4 = f & 63;
            ow[f] = *(float4*)&K[row * P1S + c4 * 4];
            ou[f] = *(float4*)&V[row * P1S + c4 * 4];
        }
    }
}

// ============================================================================
// Phase 2: sequential scan over chunks. Grid = (NJB, BHT) = 128 CTAs,
// 512 threads (16 warps/SM) for latency hiding; smem single-copy.
// GEMM-A splits the d-dimension across thread halves (disjoint loads),
// GEMM-C splits each S row's d-range 16-wide per thread.
// ============================================================================
#define P2S 260

__global__ __launch_bounds__(512, 1)
void phase2(float* __restrict__ out, int write_state)
{
    const int jb = blockIdx.x;
    const int bh = blockIdx.y;
    extern __shared__ float sm[];
    float* Wt   = sm;                          // 32 * 260
    float* Qt   = Wt + 32 * P2S;
    float* Kt   = Qt + 32 * P2S;
    float* St   = Kt + 32 * P2S;               // 32 * 256 (S^T, swizzled)
    float* Usl  = St + 32 * 256;               // 32 * 36 each below
    float* ATTs = Usl  + 32 * 36;
    float* WSl  = ATTs + 32 * 36;
    float* WSh  = WSl  + 32 * 36;
    float* QSl  = WSh  + 32 * 36;
    float* QSh  = QSl  + 32 * 36;
    float* UADJ = QSh  + 32 * 36;

    const int t = threadIdx.x;

    // zero S
#pragma unroll
    for (int r = 0; r < 16; r++) St[t + r * 512] = 0.f;
    __syncthreads();

    // GEMM-A map: 2x2 (i,j) tile; thread halves split d
    const int half = t >> 8, tt = t & 255;
    const int ip = tt >> 4, jp = tt & 15;
    const int i0 = 2 * ip, i1 = i0 + 1;
    const int j0 = 2 * jp, j1 = j0 + 1;
    const int keyA = jp & 7;
    const int d4base = half << 5;              // 16B-unit offset: 0 or 32
    // GEMM-C map: thread owns (row jj of S^T, 16-wide d block dgh)
    const int jj = t & 31, dgh = t >> 5;       // dgh in [0,16)
    const int keyC = (jj >> 1) & 7;
    // epilogue map
    const int ei = t >> 4, ej = (t & 15) * 2;

    for (int ch = 0; ch < NCH; ch++) {
        // ---- load chunk tiles ----
        {
            const size_t base = ((size_t)bh * LSEQ + (size_t)ch * CCH) * DKV;
            const float4* w4 = (const float4*)(g_w + base);
            const float4* q4 = (const float4*)(g_qn + base);
            const float4* k4 = (const float4*)(g_kn + base);
#pragma unroll
            for (int r = 0; r < 4; r++) {
                int f   = t + r * 512;
                int row = f >> 6, c4 = f & 63;
                *(float4*)&Wt[row * P2S + c4 * 4] = w4[f];
                *(float4*)&Qt[row * P2S + c4 * 4] = q4[f];
                *(float4*)&Kt[row * P2S + c4 * 4] = k4[f];
            }
            *(float2*)&Usl[ei * 36 + ej] =
                *(const float2*)&g_u[base + (size_t)ei * DKV + jb * JBW + ej];
            *(float2*)&ATTs[ei * 36 + ej] =
                *(const float2*)&g_att[((size_t)(bh * NCH + ch)) * 1024 + ei * 32 + ej];
        }
        __syncthreads();

        // ---- GEMM A: WS = w @ S, QS = q @ S  (f32x2, d-split halves) ----
        {
            unsigned long long w00 = 0, w01 = 0, w10 = 0, w11 = 0;
            unsigned long long p00 = 0, p01 = 0, p10 = 0, p11 = 0;
            const ulonglong2* wr0 = (const ulonglong2*)&Wt[i0 * P2S];
            const ulonglong2* wr1 = (const ulonglong2*)&Wt[i1 * P2S];
            const ulonglong2* qr0 = (const ulonglong2*)&Qt[i0 * P2S];
            const ulonglong2* qr1 = (const ulonglong2*)&Qt[i1 * P2S];
            const float* sr0 = &St[j0 * 256];
            const float* sr1 = &St[j1 * 256];
#pragma unroll 2
            for (int d4r = 0; d4r < 32; d4r++) {
                int d4 = d4base + d4r;
                int u  = d4 ^ keyA;
                ulonglong2 sv0 = *(const ulonglong2*)&sr0[u << 2];
                ulonglong2 sv1 = *(const ulonglong2*)&sr1[u << 2];
                ulonglong2 wv0 = wr0[d4];
                ulonglong2 wv1 = wr1[d4];
                ulonglong2 qv0 = qr0[d4];
                ulonglong2 qv1 = qr1[d4];
                w00 = ffma2(wv0.x, sv0.x, w00); w00 = ffma2(wv0.y, sv0.y, w00);
                w01 = ffma2(wv0.x, sv1.x, w01); w01 = ffma2(wv0.y, sv1.y, w01);
                w10 = ffma2(wv1.x, sv0.x, w10); w10 = ffma2(wv1.y, sv0.y, w10);
                w11 = ffma2(wv1.x, sv1.x, w11); w11 = ffma2(wv1.y, sv1.y, w11);
                p00 = ffma2(qv0.x, sv0.x, p00); p00 = ffma2(qv0.y, sv0.y, p00);
                p01 = ffma2(qv0.x, sv1.x, p01); p01 = ffma2(qv0.y, sv1.y, p01);
                p10 = ffma2(qv1.x, sv0.x, p10); p10 = ffma2(qv1.y, sv0.y, p10);
                p11 = ffma2(qv1.x, sv1.x, p11); p11 = ffma2(qv1.y, sv1.y, p11);
            }
            float* WSd = half ? WSh : WSl;
            float* QSd = half ? QSh : QSl;
            WSd[i0 * 36 + j0] = fold2(w00);
            WSd[i0 * 36 + j1] = fold2(w01);
            WSd[i1 * 36 + j0] = fold2(w10);
            WSd[i1 * 36 + j1] = fold2(w11);
            QSd[i0 * 36 + j0] = fold2(p00);
            QSd[i0 * 36 + j1] = fold2(p01);
            QSd[i1 * 36 + j0] = fold2(p10);
            QSd[i1 * 36 + j1] = fold2(p11);
        }
        __syncthreads();

        // ---- UADJ = u - WS_lo - WS_hi ----
        {
            float2 uu = *(float2*)&Usl[ei * 36 + ej];
            float2 wl = *(float2*)&WSl[ei * 36 + ej];
            float2 wh = *(float2*)&WSh[ei * 36 + ej];
            float2 r;
            r.x = uu.x - wl.x - wh.x;
            r.y = uu.y - wl.y - wh.y;
            *(float2*)&UADJ[ei * 36 + ej] = r;
        }
        __syncthreads();

        // ---- O = QS + att @ UADJ ; write to global ----
        {
            float2 ql = *(float2*)&QSl[ei * 36 + ej];
            float2 qh = *(float2*)&QSh[ei * 36 + ej];
            float2 o;
            o.x = ql.x + qh.x;
            o.y = ql.y + qh.y;
#pragma unroll 8
            for (int ii = 0; ii < CCH; ii++) {
                float a = ATTs[ei * 36 + ii];   // zero above diag
                float2 ub = *(float2*)&UADJ[ii * 36 + ej];
                o.x += a * ub.x;
                o.y += a * ub.y;
            }
            *(float2*)&out[((size_t)bh * LSEQ + (size_t)ch * CCH + ei) * DKV +
                           jb * JBW + ej] = o;
        }

        // ---- GEMM C: S += k^T @ UADJ  (register-resident RMW) ----
        {
            ulonglong2 sa[4];
            float* srow = &St[jj * 256];
#pragma unroll
            for (int m = 0; m < 4; m++) {
                int u = (dgh * 4 + m) ^ keyC;
                sa[m] = *(const ulonglong2*)&srow[u << 2];
            }
#pragma unroll 4
            for (int i = 0; i < CCH; i++) {
                unsigned long long us = splat2(UADJ[i * 36 + jj]);
                const ulonglong2* kr = (const ulonglong2*)&Kt[i * P2S + dgh * 16];
#pragma unroll
                for (int m = 0; m < 4; m++) {
                    ulonglong2 kv = kr[m];
                    sa[m].x = ffma2(kv.x, us, sa[m].x);
                    sa[m].y = ffma2(kv.y, us, sa[m].y);
                }
            }
#pragma unroll
            for (int m = 0; m < 4; m++) {
                int u = (dgh * 4 + m) ^ keyC;
                *(ulonglong2*)&srow[u << 2] = sa[m];
            }
        }
        __syncthreads();
    }

    // ---- final state S (second tuple element) ----
    if (write_state) {
        const size_t soff = OUT_ELEMS;
#pragma unroll 4
        for (int m = 0; m < 16; m++) {
            int d  = dgh * 16 + m;
            int u  = (dgh * 4 + (m >> 2)) ^ keyC;
            float val = St[jj * 256 + (u << 2) + (m & 3)];
            out[soff + ((size_t)bh * DKV + d) * DKV + jb * JBW + jj] = val;
        }
    }
}

// ============================================================================

#define SM1_BYTES ((32 * P1S * 3 + 32 * 36 + 512 + 32 + 64) * sizeof(float))
#define SM2_BYTES ((32 * P2S * 3 + 32 * 256 + 7 * 32 * 36) * sizeof(float))

extern "C" void kernel_launch(void* const* d_in, const int* in_sizes, int n_in,
                              void* d_out, int out_size)
{
    const float* q    = (const float*)d_in[0];
    const float* k    = (const float*)d_in[1];
    const float* v    = (const float*)d_in[2];
    const float* beta = (const float*)d_in[3];
    float* out = (float*)d_out;

    cudaFuncSetAttribute(phase1, cudaFuncAttributeMaxDynamicSharedMemorySize, SM1_BYTES);
    cudaFuncSetAttribute(phase2, cudaFuncAttributeMaxDynamicSharedMemorySize, SM2_BYTES);

    phase1<<<dim3(NCH, BHT), 256, SM1_BYTES>>>(q, k, v, beta);

    int ws = ((size_t)out_size >= OUT_ELEMS + STATE_ELEMS) ? 1 : 0;
    phase2<<<dim3(NJB, BHT), 512, SM2_BYTES>>>(out, ws);
}

// round 11
// speedup vs baseline: 1.2144x; 1.1127x over previous
#include <cuda_runtime.h>

// DeltaNet chunkwise delta rule.
// Shapes fixed by the problem: b=4, h=4, L=4096, dk=dv=256, chunk=32.

#define LSEQ  4096
#define DKV   256
#define CCH   32
#define NCH   (LSEQ / CCH)      // 128 chunks
#define BHT   16                // b*h
#define JBW   32                // dv block width in phase 2
#define NJB   (DKV / JBW)       // 8 column blocks

#define OUT_ELEMS   ((size_t)BHT * LSEQ * DKV)        // 16777216
#define STATE_ELEMS ((size_t)BHT * DKV * DKV)         // 1048576

// Scratch (device globals; no allocation allowed)
__device__ float g_qn [(size_t)BHT * LSEQ * DKV];
__device__ float g_kn [(size_t)BHT * LSEQ * DKV];
__device__ float g_w  [(size_t)BHT * LSEQ * DKV];
__device__ float g_u  [(size_t)BHT * LSEQ * DKV];
__device__ float g_att[(size_t)BHT * NCH * CCH * CCH];

// ---- packed f32x2 helpers (2x FFMA throughput vs 3-reg FFMA on sm_103a) ----
__device__ __forceinline__ unsigned long long ffma2(unsigned long long a,
                                                    unsigned long long b,
                                                    unsigned long long c) {
    unsigned long long d;
    asm("fma.rn.f32x2 %0, %1, %2, %3;" : "=l"(d) : "l"(a), "l"(b), "l"(c));
    return d;
}
__device__ __forceinline__ unsigned long long splat2(float x) {
    unsigned long long d;
    unsigned int r = __float_as_uint(x);
    asm("mov.b64 %0, {%1, %1};" : "=l"(d) : "r"(r));
    return d;
}
__device__ __forceinline__ float fold2(unsigned long long a) {
    unsigned int lo, hi;
    asm("mov.b64 {%0, %1}, %2;" : "=r"(lo), "=r"(hi) : "l"(a));
    return __uint_as_float(lo) + __uint_as_float(hi);
}

// ---- cp.async: global -> shared 16B, no register round-trip ----
__device__ __forceinline__ void cpa16(void* smem_dst, const void* gmem_src) {
    unsigned int s = (unsigned int)__cvta_generic_to_shared(smem_dst);
    asm volatile("cp.async.ca.shared.global [%0], [%1], 16;" :: "r"(s), "l"(gmem_src));
}
__device__ __forceinline__ void cpa_commit_wait() {
    asm volatile("cp.async.commit_group;");
    asm volatile("cp.async.wait_group 0;" ::: "memory");
}

// ============================================================================
// Phase 1: per-chunk preprocessing (parallel over bh * chunks = 2048 CTAs).
//   qn = l2norm(q); kn = l2norm(k); vb = v*beta
//   A  = strict_tril(beta_i * kn_i . kn_j); att = tril(qn @ kn^T)
//   w  = (I+A)^-1 (kn*beta), u = (I+A)^-1 vb  -- register-resident forward
//   substitution per column (no barriers), stored straight to global.
// ============================================================================
#define P1S 260

__global__ __launch_bounds__(256, 2)
void phase1(const float* __restrict__ q, const float* __restrict__ k,
            const float* __restrict__ v, const float* __restrict__ beta)
{
    const int ch = blockIdx.x;
    const int bh = blockIdx.y;
    extern __shared__ float sm[];
    float* Q   = sm;                         // 32 * 260
    float* K   = Q + 32 * P1S;
    float* V   = K + 32 * P1S;
    float* A   = V + 32 * P1S;               // 32 * 36
    float* RED = A + 32 * 36;                // 512
    float* BET = RED + 512;                  // 32
    float* NRM = BET + 32;                   // 64

    const int t = threadIdx.x;
    const size_t base = ((size_t)bh * LSEQ + (size_t)ch * CCH) * DKV;
    const float4* q4 = (const float4*)(q + base);
    const float4* k4 = (const float4*)(k + base);
    const float4* v4 = (const float4*)(v + base);

    // load tiles (2048 float4 each, 8 per thread) via cp.async
#pragma unroll
    for (int r = 0; r < 8; r++) {
        int f   = t + r * 256;
        int row = f >> 6, c4 = f & 63;
        cpa16(&Q[row * P1S + c4 * 4], &q4[f]);
        cpa16(&K[row * P1S + c4 * 4], &k4[f]);
        cpa16(&V[row * P1S + c4 * 4], &v4[f]);
    }
    if (t < CCH) BET[t] = beta[(size_t)bh * LSEQ + ch * CCH + t];
    cpa_commit_wait();
    __syncthreads();

    // row sum-of-squares for q and k
    {
        int r = t >> 3, s = t & 7;
        float aq = 0.f, ak = 0.f;
#pragma unroll
        for (int m = 0; m < 32; m++) {
            float xq = Q[r * P1S + s * 32 + m];
            float xk = K[r * P1S + s * 32 + m];
            aq += xq * xq;
            ak += xk * xk;
        }
        RED[r * 8 + s]       = aq;
        RED[256 + r * 8 + s] = ak;
    }
    __syncthreads();
    if (t < 64) {
        int r = t & 31, wsel = t >> 5;
        float ssum = 0.f;
#pragma unroll
        for (int s = 0; s < 8; s++) ssum += RED[wsel * 256 + r * 8 + s];
        NRM[t] = rsqrtf(ssum);
    }
    __syncthreads();

    // normalize q,k (write qn,kn straight to global) ; v *= beta
    {
        float4* oq = (float4*)(g_qn + base);
        float4* ok = (float4*)(g_kn + base);
#pragma unroll
        for (int r = 0; r < 8; r++) {
            int f   = t + r * 256;
            int row = f >> 6, c4 = f & 63;
            float nq = NRM[row], nk = NRM[32 + row], be = BET[row];
            float4 xq = *(float4*)&Q[row * P1S + c4 * 4];
            xq.x *= nq; xq.y *= nq; xq.z *= nq; xq.w *= nq;
            *(float4*)&Q[row * P1S + c4 * 4] = xq;
            oq[f] = xq;
            float4 xk = *(float4*)&K[row * P1S + c4 * 4];
            xk.x *= nk; xk.y *= nk; xk.z *= nk; xk.w *= nk;
            *(float4*)&K[row * P1S + c4 * 4] = xk;
            ok[f] = xk;
            float4 xv = *(float4*)&V[row * P1S + c4 * 4];
            xv.x *= be; xv.y *= be; xv.z *= be; xv.w *= be;
            *(float4*)&V[row * P1S + c4 * 4] = xv;
        }
    }
    __syncthreads();

    // A (strict lower, beta_i * kn_i . kn_j) and att (tril incl diag).
    // Warp covers 4 i-rows x 8 j-slots; thread owns (i, 4 j's strided by 8):
    // all 6 LDS.128 per d4 iteration are single-wavefront.
    {
        const int w8 = t >> 5, la = t & 31;
        const int i  = w8 * 4 + (la >> 3);
        const int jq = la & 7;
        float dkk0 = 0.f, dkk1 = 0.f, dkk2 = 0.f, dkk3 = 0.f;
        float dqk0 = 0.f, dqk1 = 0.f, dqk2 = 0.f, dqk3 = 0.f;
        const float* Ki = &K[i * P1S];
        const float* Qi = &Q[i * P1S];
        const float* Kj0 = &K[(jq     ) * P1S];
        const float* Kj1 = &K[(jq +  8) * P1S];
        const float* Kj2 = &K[(jq + 16) * P1S];
        const float* Kj3 = &K[(jq + 24) * P1S];
#pragma unroll 8
        for (int d4 = 0; d4 < 64; d4++) {
            float4 ki = *(const float4*)&Ki[d4 * 4];
            float4 qi = *(const float4*)&Qi[d4 * 4];
            float4 a0 = *(const float4*)&Kj0[d4 * 4];
            float4 a1 = *(const float4*)&Kj1[d4 * 4];
            float4 a2 = *(const float4*)&Kj2[d4 * 4];
            float4 a3 = *(const float4*)&Kj3[d4 * 4];
            dkk0 += ki.x*a0.x + ki.y*a0.y + ki.z*a0.z + ki.w*a0.w;
            dkk1 += ki.x*a1.x + ki.y*a1.y + ki.z*a1.z + ki.w*a1.w;
            dkk2 += ki.x*a2.x + ki.y*a2.y + ki.z*a2.z + ki.w*a2.w;
            dkk3 += ki.x*a3.x + ki.y*a3.y + ki.z*a3.z + ki.w*a3.w;
            dqk0 += qi.x*a0.x + qi.y*a0.y + qi.z*a0.z + qi.w*a0.w;
            dqk1 += qi.x*a1.x + qi.y*a1.y + qi.z*a1.z + qi.w*a1.w;
            dqk2 += qi.x*a2.x + qi.y*a2.y + qi.z*a2.z + qi.w*a2.w;
            dqk3 += qi.x*a3.x + qi.y*a3.y + qi.z*a3.z + qi.w*a3.w;
        }
        float bi = BET[i];
        float* attg = g_att + ((size_t)(bh * NCH + ch)) * (CCH * CCH) + i * 32;
        int j;
        j = jq;      A[i*36+j] = (j <  i) ? bi*dkk0 : 0.f; attg[j] = (j <= i) ? dqk0 : 0.f;
        j = jq + 8;  A[i*36+j] = (j <  i) ? bi*dkk1 : 0.f; attg[j] = (j <= i) ? dqk1 : 0.f;
        j = jq + 16; A[i*36+j] = (j <  i) ? bi*dkk2 : 0.f; attg[j] = (j <= i) ? dqk2 : 0.f;
        j = jq + 24; A[i*36+j] = (j <  i) ? bi*dkk3 : 0.f; attg[j] = (j <= i) ? dqk3 : 0.f;
    }
    __syncthreads();

    // Forward substitution, fully register-resident per column (no barriers).
    // Thread t owns column t of w (from beta*kn) and u (from beta*v).
    {
        float rk[32], rv[32];
        float* ow = g_w + base + t;
        float* ou = g_u + base + t;
#pragma unroll
        for (int i = 0; i < 32; i++) {
            float accw = BET[i] * K[i * P1S + t];
            float accv = V[i * P1S + t];
            const int i4 = i >> 2;
#pragma unroll
            for (int b = 0; b < i4; b++) {
                float4 a = *(const float4*)&A[i * 36 + b * 4];
                accw -= a.x * rk[b*4+0] + a.y * rk[b*4+1]
                      + a.z * rk[b*4+2] + a.w * rk[b*4+3];
                accv -= a.x * rv[b*4+0] + a.y * rv[b*4+1]
                      + a.z * rv[b*4+2] + a.w * rv[b*4+3];
            }
#pragma unroll
            for (int j = i4 * 4; j < i; j++) {
                float a = A[i * 36 + j];
                accw -= a * rk[j];
                accv -= a * rv[j];
            }
            rk[i] = accw;
            rv[i] = accv;
            ow[(size_t)i * DKV] = accw;
            ou[(size_t)i * DKV] = accv;
        }
    }
}

// ============================================================================
// Phase 2: sequential scan over chunks. Grid = (NJB, BHT) = 128 CTAs,
// 512 threads; smem single-copy. GEMM-A warp tile 4ip x 8jp (every LDS.128
// is one wavefront); GEMM-C register-resident S RMW; epilogue float4/256thr.
// ============================================================================
#define P2S 260

__global__ __launch_bounds__(512, 1)
void phase2(float* __restrict__ out, int write_state)
{
    const int jb = blockIdx.x;
    const int bh = blockIdx.y;
    extern __shared__ float sm[];
    float* Wt   = sm;                          // 32 * 260
    float* Qt   = Wt + 32 * P2S;
    float* Kt   = Qt + 32 * P2S;
    float* St   = Kt + 32 * P2S;               // 32 * 256 (S^T, swizzled)
    float* Usl  = St + 32 * 256;               // 32 * 36 each below
    float* ATTs = Usl  + 32 * 36;
    float* WSl  = ATTs + 32 * 36;
    float* WSh  = WSl  + 32 * 36;
    float* QSl  = WSh  + 32 * 36;
    float* QSh  = QSl  + 32 * 36;
    float* UADJ = QSh  + 32 * 36;

    const int t = threadIdx.x;

    // zero S
#pragma unroll
    for (int r = 0; r < 16; r++) St[t + r * 512] = 0.f;
    __syncthreads();

    // GEMM-A map: 2x2 (i,j) tile; halves split d; warp covers 4 ip x 8 jp
    const int half = t >> 8, tt = t & 255;
    const int w8 = tt >> 5, la = tt & 31;
    const int ip = (w8 >> 1) * 4 + (la >> 3);
    const int jp = (w8 & 1) * 8 + (la & 7);
    const int i0 = 2 * ip, i1 = i0 + 1;
    const int j0 = 2 * jp, j1 = j0 + 1;
    const int keyA = jp & 7;
    const int d4base = half << 5;              // 16B-unit offset: 0 or 32
    // GEMM-C map: thread owns (row jj of S^T, 16-wide d block dgh)
    const int jj = t & 31, dgh = t >> 5;       // dgh in [0,16)
    const int keyC = (jj >> 1) & 7;
    // epilogue/merge map (256 threads, float4)
    const int ei = (t & 255) >> 3, ej4 = (t & 7) * 4;

    for (int ch = 0; ch < NCH; ch++) {
        // ---- load chunk tiles (cp.async, no register round-trip) ----
        {
            const size_t base = ((size_t)bh * LSEQ + (size_t)ch * CCH) * DKV;
            const float4* w4 = (const float4*)(g_w + base);
            const float4* q4 = (const float4*)(g_qn + base);
            const float4* k4 = (const float4*)(g_kn + base);
#pragma unroll
            for (int r = 0; r < 4; r++) {
                int f   = t + r * 512;
                int row = f >> 6, c4 = f & 63;
                cpa16(&Wt[row * P2S + c4 * 4], &w4[f]);
                cpa16(&Qt[row * P2S + c4 * 4], &q4[f]);
                cpa16(&Kt[row * P2S + c4 * 4], &k4[f]);
            }
            if (t < 256) {
                cpa16(&Usl[ei * 36 + ej4],
                      &g_u[base + (size_t)ei * DKV + jb * JBW + ej4]);
                cpa16(&ATTs[ei * 36 + ej4],
                      &g_att[((size_t)(bh * NCH + ch)) * 1024 + ei * 32 + ej4]);
            }
            cpa_commit_wait();
        }
        __syncthreads();

        // ---- GEMM A: WS = w @ S, QS = q @ S  (f32x2, d-split halves) ----
        {
            unsigned long long w00 = 0, w01 = 0, w10 = 0, w11 = 0;
            unsigned long long p00 = 0, p01 = 0, p10 = 0, p11 = 0;
            const ulonglong2* wr0 = (const ulonglong2*)&Wt[i0 * P2S];
            const ulonglong2* wr1 = (const ulonglong2*)&Wt[i1 * P2S];
            const ulonglong2* qr0 = (const ulonglong2*)&Qt[i0 * P2S];
            const ulonglong2* qr1 = (const ulonglong2*)&Qt[i1 * P2S];
            const float* sr0 = &St[j0 * 256];
            const float* sr1 = &St[j1 * 256];
#pragma unroll 2
            for (int d4r = 0; d4r < 32; d4r++) {
                int d4 = d4base + d4r;
                int u  = d4 ^ keyA;
                ulonglong2 sv0 = *(const ulonglong2*)&sr0[u << 2];
                ulonglong2 sv1 = *(const ulonglong2*)&sr1[u << 2];
                ulonglong2 wv0 = wr0[d4];
                ulonglong2 wv1 = wr1[d4];
                ulonglong2 qv0 = qr0[d4];
                ulonglong2 qv1 = qr1[d4];
                w00 = ffma2(wv0.x, sv0.x, w00); w00 = ffma2(wv0.y, sv0.y, w00);
                w01 = ffma2(wv0.x, sv1.x, w01); w01 = ffma2(wv0.y, sv1.y, w01);
                w10 = ffma2(wv1.x, sv0.x, w10); w10 = ffma2(wv1.y, sv0.y, w10);
                w11 = ffma2(wv1.x, sv1.x, w11); w11 = ffma2(wv1.y, sv1.y, w11);
                p00 = ffma2(qv0.x, sv0.x, p00); p00 = ffma2(qv0.y, sv0.y, p00);
                p01 = ffma2(qv0.x, sv1.x, p01); p01 = ffma2(qv0.y, sv1.y, p01);
                p10 = ffma2(qv1.x, sv0.x, p10); p10 = ffma2(qv1.y, sv0.y, p10);
                p11 = ffma2(qv1.x, sv1.x, p11); p11 = ffma2(qv1.y, sv1.y, p11);
            }
            float* WSd = half ? WSh : WSl;
            float* QSd = half ? QSh : QSl;
            WSd[i0 * 36 + j0] = fold2(w00);
            WSd[i0 * 36 + j1] = fold2(w01);
            WSd[i1 * 36 + j0] = fold2(w10);
            WSd[i1 * 36 + j1] = fold2(w11);
            QSd[i0 * 36 + j0] = fold2(p00);
            QSd[i0 * 36 + j1] = fold2(p01);
            QSd[i1 * 36 + j0] = fold2(p10);
            QSd[i1 * 36 + j1] = fold2(p11);
        }
        __syncthreads();

        // ---- UADJ = u - WS_lo - WS_hi (256 threads, float4) ----
        if (t < 256) {
            float4 uu = *(float4*)&Usl[ei * 36 + ej4];
            float4 wl = *(float4*)&WSl[ei * 36 + ej4];
            float4 wh = *(float4*)&WSh[ei * 36 + ej4];
            float4 r;
            r.x = uu.x - wl.x - wh.x;
            r.y = uu.y - wl.y - wh.y;
            r.z = uu.z - wl.z - wh.z;
            r.w = uu.w - wl.w - wh.w;
            *(float4*)&UADJ[ei * 36 + ej4] = r;
        }
        __syncthreads();

        // ---- O = QS + att @ UADJ ; write to global (256 threads, float4) ----
        if (t < 256) {
            float4 ql = *(float4*)&QSl[ei * 36 + ej4];
            float4 qh = *(float4*)&QSh[ei * 36 + ej4];
            float4 o;
            o.x = ql.x + qh.x; o.y = ql.y + qh.y;
            o.z = ql.z + qh.z; o.w = ql.w + qh.w;
#pragma unroll 8
            for (int ii = 0; ii < CCH; ii++) {
                float a = ATTs[ei * 36 + ii];   // zero above diag
                float4 ub = *(float4*)&UADJ[ii * 36 + ej4];
                o.x += a * ub.x; o.y += a * ub.y;
                o.z += a * ub.z; o.w += a * ub.w;
            }
            *(float4*)&out[((size_t)bh * LSEQ + (size_t)ch * CCH + ei) * DKV +
                           jb * JBW + ej4] = o;
        }

        // ---- GEMM C: S += k^T @ UADJ  (register-resident RMW) ----
        {
            ulonglong2 sa[4];
            float* srow = &St[jj * 256];
#pragma unroll
            for (int m = 0; m < 4; m++) {
                int u = (dgh * 4 + m) ^ keyC;
                sa[m] = *(const ulonglong2*)&srow[u << 2];
            }
#pragma unroll 4
            for (int i = 0; i < CCH; i++) {
                unsigned long long us = splat2(UADJ[i * 36 + jj]);
                const ulonglong2* kr = (const ulonglong2*)&Kt[i * P2S + dgh * 16];
#pragma unroll
                for (int m = 0; m < 4; m++) {
                    ulonglong2 kv = kr[m];
                    sa[m].x = ffma2(kv.x, us, sa[m].x);
                    sa[m].y = ffma2(kv.y, us, sa[m].y);
                }
            }
#pragma unroll
            for (int m = 0; m < 4; m++) {
                int u = (dgh * 4 + m) ^ keyC;
                *(ulonglong2*)&srow[u << 2] = sa[m];
            }
        }
        __syncthreads();
    }

    // ---- final state S (second tuple element) ----
    if (write_state) {
        const size_t soff = OUT_ELEMS;
#pragma unroll 4
        for (int m = 0; m < 16; m++) {
            int d  = dgh * 16 + m;
            int u  = (dgh * 4 + (m >> 2)) ^ keyC;
            float val = St[jj * 256 + (u << 2) + (m & 3)];
            out[soff + ((size_t)bh * DKV + d) * DKV + jb * JBW + jj] = val;
        }
    }
}

// ============================================================================

#define SM1_BYTES ((32 * P1S * 3 + 32 * 36 + 512 + 32 + 64) * sizeof(float))
#define SM2_BYTES ((32 * P2S * 3 + 32 * 256 + 7 * 32 * 36) * sizeof(float))

extern "C" void kernel_launch(void* const* d_in, const int* in_sizes, int n_in,
                              void* d_out, int out_size)
{
    const float* q    = (const float*)d_in[0];
    const float* k    = (const float*)d_in[1];
    const float* v    = (const float*)d_in[2];
    const float* beta = (const float*)d_in[3];
    float* out = (float*)d_out;

    cudaFuncSetAttribute(phase1, cudaFuncAttributeMaxDynamicSharedMemorySize, SM1_BYTES);
    cudaFuncSetAttribute(phase2, cudaFuncAttributeMaxDynamicSharedMemorySize, SM2_BYTES);

    phase1<<<dim3(NCH, BHT), 256, SM1_BYTES>>>(q, k, v, beta);

    int ws = ((size_t)out_size >= OUT_ELEMS + STATE_ELEMS) ? 1 : 0;
    phase2<<<dim3(NJB, BHT), 512, SM2_BYTES>>>(out, ws);
}

// round 12
// speedup vs baseline: 1.2299x; 1.0128x over previous
#include <cuda_runtime.h>

// DeltaNet chunkwise delta rule.
// Shapes fixed by the problem: b=4, h=4, L=4096, dk=dv=256, chunk=32.

#define LSEQ  4096
#define DKV   256
#define CCH   32
#define NCH   (LSEQ / CCH)      // 128 chunks
#define BHT   16                // b*h
#define JBW   32                // dv block width in phase 2
#define NJB   (DKV / JBW)       // 8 column blocks

#define OUT_ELEMS   ((size_t)BHT * LSEQ * DKV)        // 16777216
#define STATE_ELEMS ((size_t)BHT * DKV * DKV)         // 1048576

// Scratch (device globals; no allocation allowed)
__device__ float g_qn [(size_t)BHT * LSEQ * DKV];
__device__ float g_kn [(size_t)BHT * LSEQ * DKV];
__device__ float g_w  [(size_t)BHT * LSEQ * DKV];
__device__ float g_u  [(size_t)BHT * LSEQ * DKV];
__device__ float g_att[(size_t)BHT * NCH * CCH * CCH];

// ---- packed f32x2 helpers (2x FFMA throughput vs 3-reg FFMA on sm_103a) ----
__device__ __forceinline__ unsigned long long ffma2(unsigned long long a,
                                                    unsigned long long b,
                                                    unsigned long long c) {
    unsigned long long d;
    asm("fma.rn.f32x2 %0, %1, %2, %3;" : "=l"(d) : "l"(a), "l"(b), "l"(c));
    return d;
}
__device__ __forceinline__ unsigned long long splat2(float x) {
    unsigned long long d;
    unsigned int r = __float_as_uint(x);
    asm("mov.b64 %0, {%1, %1};" : "=l"(d) : "r"(r));
    return d;
}
__device__ __forceinline__ float fold2(unsigned long long a) {
    unsigned int lo, hi;
    asm("mov.b64 {%0, %1}, %2;" : "=r"(lo), "=r"(hi) : "l"(a));
    return __uint_as_float(lo) + __uint_as_float(hi);
}

// ---- cp.async: global -> shared 16B, no register round-trip ----
__device__ __forceinline__ void cpa16(void* smem_dst, const void* gmem_src) {
    unsigned int s = (unsigned int)__cvta_generic_to_shared(smem_dst);
    asm volatile("cp.async.ca.shared.global [%0], [%1], 16;" :: "r"(s), "l"(gmem_src));
}
__device__ __forceinline__ void cpa_commit() {
    asm volatile("cp.async.commit_group;");
}
__device__ __forceinline__ void cpa_wait_all() {
    asm volatile("cp.async.wait_group 0;" ::: "memory");
}

// ============================================================================
// Phase 1: per-chunk preprocessing (parallel over bh * chunks = 2048 CTAs).
//   qn = l2norm(q); kn = l2norm(k); vb = v*beta
//   A  = strict_tril(beta_i * kn_i . kn_j); att = tril(qn @ kn^T)
//   w  = (I+A)^-1 (kn*beta), u = (I+A)^-1 vb  -- register-resident forward
//   substitution per column (no barriers), stored straight to global.
// ============================================================================
#define P1S 260

__global__ __launch_bounds__(256, 2)
void phase1(const float* __restrict__ q, const float* __restrict__ k,
            const float* __restrict__ v, const float* __restrict__ beta)
{
    const int ch = blockIdx.x;
    const int bh = blockIdx.y;
    extern __shared__ float sm[];
    float* Q   = sm;                         // 32 * 260
    float* K   = Q + 32 * P1S;
    float* V   = K + 32 * P1S;
    float* A   = V + 32 * P1S;               // 32 * 36
    float* RED = A + 32 * 36;                // 512
    float* BET = RED + 512;                  // 32
    float* NRM = BET + 32;                   // 64

    const int t = threadIdx.x;
    const size_t base = ((size_t)bh * LSEQ + (size_t)ch * CCH) * DKV;
    const float4* q4 = (const float4*)(q + base);
    const float4* k4 = (const float4*)(k + base);
    const float4* v4 = (const float4*)(v + base);

    // load tiles (2048 float4 each, 8 per thread) via cp.async
#pragma unroll
    for (int r = 0; r < 8; r++) {
        int f   = t + r * 256;
        int row = f >> 6, c4 = f & 63;
        cpa16(&Q[row * P1S + c4 * 4], &q4[f]);
        cpa16(&K[row * P1S + c4 * 4], &k4[f]);
        cpa16(&V[row * P1S + c4 * 4], &v4[f]);
    }
    if (t < CCH) BET[t] = beta[(size_t)bh * LSEQ + ch * CCH + t];
    cpa_commit();
    cpa_wait_all();
    __syncthreads();

    // row sum-of-squares for q and k
    {
        int r = t >> 3, s = t & 7;
        float aq = 0.f, ak = 0.f;
#pragma unroll
        for (int m = 0; m < 32; m++) {
            float xq = Q[r * P1S + s * 32 + m];
            float xk = K[r * P1S + s * 32 + m];
            aq += xq * xq;
            ak += xk * xk;
        }
        RED[r * 8 + s]       = aq;
        RED[256 + r * 8 + s] = ak;
    }
    __syncthreads();
    if (t < 64) {
        int r = t & 31, wsel = t >> 5;
        float ssum = 0.f;
#pragma unroll
        for (int s = 0; s < 8; s++) ssum += RED[wsel * 256 + r * 8 + s];
        NRM[t] = rsqrtf(ssum);
    }
    __syncthreads();

    // normalize q,k (write qn,kn straight to global) ; v *= beta
    {
        float4* oq = (float4*)(g_qn + base);
        float4* ok = (float4*)(g_kn + base);
#pragma unroll
        for (int r = 0; r < 8; r++) {
            int f   = t + r * 256;
            int row = f >> 6, c4 = f & 63;
            float nq = NRM[row], nk = NRM[32 + row], be = BET[row];
            float4 xq = *(float4*)&Q[row * P1S + c4 * 4];
            xq.x *= nq; xq.y *= nq; xq.z *= nq; xq.w *= nq;
            *(float4*)&Q[row * P1S + c4 * 4] = xq;
            oq[f] = xq;
            float4 xk = *(float4*)&K[row * P1S + c4 * 4];
            xk.x *= nk; xk.y *= nk; xk.z *= nk; xk.w *= nk;
            *(float4*)&K[row * P1S + c4 * 4] = xk;
            ok[f] = xk;
            float4 xv = *(float4*)&V[row * P1S + c4 * 4];
            xv.x *= be; xv.y *= be; xv.z *= be; xv.w *= be;
            *(float4*)&V[row * P1S + c4 * 4] = xv;
        }
    }
    __syncthreads();

    // A (strict lower, beta_i * kn_i . kn_j) and att (tril incl diag).
    // Warp covers 4 i-rows x 8 j-slots; thread owns (i, 4 j's strided by 8).
    {
        const int w8 = t >> 5, la = t & 31;
        const int i  = w8 * 4 + (la >> 3);
        const int jq = la & 7;
        float dkk0 = 0.f, dkk1 = 0.f, dkk2 = 0.f, dkk3 = 0.f;
        float dqk0 = 0.f, dqk1 = 0.f, dqk2 = 0.f, dqk3 = 0.f;
        const float* Ki = &K[i * P1S];
        const float* Qi = &Q[i * P1S];
        const float* Kj0 = &K[(jq     ) * P1S];
        const float* Kj1 = &K[(jq +  8) * P1S];
        const float* Kj2 = &K[(jq + 16) * P1S];
        const float* Kj3 = &K[(jq + 24) * P1S];
#pragma unroll 8
        for (int d4 = 0; d4 < 64; d4++) {
            float4 ki = *(const float4*)&Ki[d4 * 4];
            float4 qi = *(const float4*)&Qi[d4 * 4];
            float4 a0 = *(const float4*)&Kj0[d4 * 4];
            float4 a1 = *(const float4*)&Kj1[d4 * 4];
            float4 a2 = *(const float4*)&Kj2[d4 * 4];
            float4 a3 = *(const float4*)&Kj3[d4 * 4];
            dkk0 += ki.x*a0.x + ki.y*a0.y + ki.z*a0.z + ki.w*a0.w;
            dkk1 += ki.x*a1.x + ki.y*a1.y + ki.z*a1.z + ki.w*a1.w;
            dkk2 += ki.x*a2.x + ki.y*a2.y + ki.z*a2.z + ki.w*a2.w;
            dkk3 += ki.x*a3.x + ki.y*a3.y + ki.z*a3.z + ki.w*a3.w;
            dqk0 += qi.x*a0.x + qi.y*a0.y + qi.z*a0.z + qi.w*a0.w;
            dqk1 += qi.x*a1.x + qi.y*a1.y + qi.z*a1.z + qi.w*a1.w;
            dqk2 += qi.x*a2.x + qi.y*a2.y + qi.z*a2.z + qi.w*a2.w;
            dqk3 += qi.x*a3.x + qi.y*a3.y + qi.z*a3.z + qi.w*a3.w;
        }
        float bi = BET[i];
        float* attg = g_att + ((size_t)(bh * NCH + ch)) * (CCH * CCH) + i * 32;
        int j;
        j = jq;      A[i*36+j] = (j <  i) ? bi*dkk0 : 0.f; attg[j] = (j <= i) ? dqk0 : 0.f;
        j = jq + 8;  A[i*36+j] = (j <  i) ? bi*dkk1 : 0.f; attg[j] = (j <= i) ? dqk1 : 0.f;
        j = jq + 16; A[i*36+j] = (j <  i) ? bi*dkk2 : 0.f; attg[j] = (j <= i) ? dqk2 : 0.f;
        j = jq + 24; A[i*36+j] = (j <  i) ? bi*dkk3 : 0.f; attg[j] = (j <= i) ? dqk3 : 0.f;
    }
    __syncthreads();

    // Forward substitution, fully register-resident per column (no barriers).
    // Thread t owns column t of w (from beta*kn) and u (from beta*v).
    {
        float rk[32], rv[32];
        float* ow = g_w + base + t;
        float* ou = g_u + base + t;
#pragma unroll
        for (int i = 0; i < 32; i++) {
            float accw = BET[i] * K[i * P1S + t];
            float accv = V[i * P1S + t];
            const int i4 = i >> 2;
#pragma unroll
            for (int b = 0; b < i4; b++) {
                float4 a = *(const float4*)&A[i * 36 + b * 4];
                accw -= a.x * rk[b*4+0] + a.y * rk[b*4+1]
                      + a.z * rk[b*4+2] + a.w * rk[b*4+3];
                accv -= a.x * rv[b*4+0] + a.y * rv[b*4+1]
                      + a.z * rv[b*4+2] + a.w * rv[b*4+3];
            }
#pragma unroll
            for (int j = i4 * 4; j < i; j++) {
                float a = A[i * 36 + j];
                accw -= a * rk[j];
                accv -= a * rv[j];
            }
            rk[i] = accw;
            rv[i] = accv;
            ow[(size_t)i * DKV] = accw;
            ou[(size_t)i * DKV] = accv;
        }
    }
}

// ============================================================================
// Phase 2: sequential scan over chunks. Grid = (NJB, BHT) = 128 CTAs,
// 512 threads. Software-pipelined: W/Q (+next usl/att) prefetched during
// GEMM-C + epilogue, K prefetched during the epilogue. Epilogue + UADJ use
// all 512 threads (float2/thread). GEMM-C S-row preload overlaps UADJ pass.
// ============================================================================
#define P2S 260

__global__ __launch_bounds__(512, 1)
void phase2(float* __restrict__ out, int write_state)
{
    const int jb = blockIdx.x;
    const int bh = blockIdx.y;
    extern __shared__ float sm[];
    float* Wt   = sm;                          // 32 * 260
    float* Qt   = Wt + 32 * P2S;
    float* Kt   = Qt + 32 * P2S;
    float* St   = Kt + 32 * P2S;               // 32 * 256 (S^T, swizzled)
    float* Usl0 = St + 32 * 256;               // 32 * 36 each below
    float* Usl1 = Usl0 + 32 * 36;
    float* ATT0 = Usl1 + 32 * 36;
    float* ATT1 = ATT0 + 32 * 36;
    float* WSl  = ATT1 + 32 * 36;
    float* WSh  = WSl  + 32 * 36;
    float* QSl  = WSh  + 32 * 36;
    float* QSh  = QSl  + 32 * 36;
    float* UADJ = QSh  + 32 * 36;

    const int t = threadIdx.x;

    // zero S
#pragma unroll
    for (int r = 0; r < 16; r++) St[t + r * 512] = 0.f;

    // GEMM-A map: 2x2 (i,j) tile; halves split d; warp covers 4 ip x 8 jp
    const int half = t >> 8, tt = t & 255;
    const int w8 = tt >> 5, la = tt & 31;
    const int ip = (w8 >> 1) * 4 + (la >> 3);
    const int jp = (w8 & 1) * 8 + (la & 7);
    const int i0 = 2 * ip, i1 = i0 + 1;
    const int j0 = 2 * jp, j1 = j0 + 1;
    const int keyA = jp & 7;
    const int d4base = half << 5;              // 16B-unit offset: 0 or 32
    // GEMM-C map: thread owns (row jj of S^T, 16-wide d block dgh)
    const int jj = t & 31, dgh = t >> 5;       // dgh in [0,16)
    const int keyC = (jj >> 1) & 7;
    // epilogue/merge map (512 threads, float2)
    const int ei = t >> 4, ej2 = (t & 15) * 2;

    const size_t bh_base  = (size_t)bh * LSEQ * DKV;
    const size_t att_base = (size_t)(bh * NCH) * 1024;

    // ---- prime pipeline: load chunk 0 tiles ----
    {
        const size_t base = bh_base;   // ch = 0
        const float4* w4 = (const float4*)(g_w + base);
        const float4* q4 = (const float4*)(g_qn + base);
        const float4* k4 = (const float4*)(g_kn + base);
#pragma unroll
        for (int r = 0; r < 4; r++) {
            int f   = t + r * 512;
            int row = f >> 6, c4 = f & 63;
            cpa16(&Wt[row * P2S + c4 * 4], &w4[f]);
            cpa16(&Qt[row * P2S + c4 * 4], &q4[f]);
            cpa16(&Kt[row * P2S + c4 * 4], &k4[f]);
        }
        if (t < 256) {
            int li = t >> 3, lj4 = (t & 7) * 4;
            cpa16(&Usl0[li * 36 + lj4], &g_u[base + (size_t)li * DKV + jb * JBW + lj4]);
            cpa16(&ATT0[li * 36 + lj4], &g_att[att_base + li * 32 + lj4]);
        }
        cpa_commit();
    }

    for (int ch = 0; ch < NCH; ch++) {
        const int p = ch & 1;
        float* Usl  = p ? Usl1 : Usl0;
        float* ATTs = p ? ATT1 : ATT0;
        float* UslN = p ? Usl0 : Usl1;
        float* ATTN = p ? ATT0 : ATT1;

        cpa_wait_all();
        __syncthreads();

        // ---- GEMM A: WS = w @ S, QS = q @ S  (f32x2, d-split halves) ----
        {
            unsigned long long w00 = 0, w01 = 0, w10 = 0, w11 = 0;
            unsigned long long p00 = 0, p01 = 0, p10 = 0, p11 = 0;
            const ulonglong2* wr0 = (const ulonglong2*)&Wt[i0 * P2S];
            const ulonglong2* wr1 = (const ulonglong2*)&Wt[i1 * P2S];
            const ulonglong2* qr0 = (const ulonglong2*)&Qt[i0 * P2S];
            const ulonglong2* qr1 = (const ulonglong2*)&Qt[i1 * P2S];
            const float* sr0 = &St[j0 * 256];
            const float* sr1 = &St[j1 * 256];
#pragma unroll 2
            for (int d4r = 0; d4r < 32; d4r++) {
                int d4 = d4base + d4r;
                int u  = d4 ^ keyA;
                ulonglong2 sv0 = *(const ulonglong2*)&sr0[u << 2];
                ulonglong2 sv1 = *(const ulonglong2*)&sr1[u << 2];
                ulonglong2 wv0 = wr0[d4];
                ulonglong2 wv1 = wr1[d4];
                ulonglong2 qv0 = qr0[d4];
                ulonglong2 qv1 = qr1[d4];
                w00 = ffma2(wv0.x, sv0.x, w00); w00 = ffma2(wv0.y, sv0.y, w00);
                w01 = ffma2(wv0.x, sv1.x, w01); w01 = ffma2(wv0.y, sv1.y, w01);
                w10 = ffma2(wv1.x, sv0.x, w10); w10 = ffma2(wv1.y, sv0.y, w10);
                w11 = ffma2(wv1.x, sv1.x, w11); w11 = ffma2(wv1.y, sv1.y, w11);
                p00 = ffma2(qv0.x, sv0.x, p00); p00 = ffma2(qv0.y, sv0.y, p00);
                p01 = ffma2(qv0.x, sv1.x, p01); p01 = ffma2(qv0.y, sv1.y, p01);
                p10 = ffma2(qv1.x, sv0.x, p10); p10 = ffma2(qv1.y, sv0.y, p10);
                p11 = ffma2(qv1.x, sv1.x, p11); p11 = ffma2(qv1.y, sv1.y, p11);
            }
            float* WSd = half ? WSh : WSl;
            float* QSd = half ? QSh : QSl;
            WSd[i0 * 36 + j0] = fold2(w00);
            WSd[i0 * 36 + j1] = fold2(w01);
            WSd[i1 * 36 + j0] = fold2(w10);
            WSd[i1 * 36 + j1] = fold2(w11);
            QSd[i0 * 36 + j0] = fold2(p00);
            QSd[i0 * 36 + j1] = fold2(p01);
            QSd[i1 * 36 + j0] = fold2(p10);
            QSd[i1 * 36 + j1] = fold2(p11);
        }
        __syncthreads();

        // ---- GEMM-C S-row preload (St stable now) overlapping UADJ pass ----
        ulonglong2 sa[4];
        {
            float* srow = &St[jj * 256];
#pragma unroll
            for (int m = 0; m < 4; m++) {
                int u = (dgh * 4 + m) ^ keyC;
                sa[m] = *(const ulonglong2*)&srow[u << 2];
            }
        }

        // ---- UADJ = u - WS_lo - WS_hi (512 threads, float2) ----
        {
            float2 uu = *(float2*)&Usl[ei * 36 + ej2];
            float2 wl = *(float2*)&WSl[ei * 36 + ej2];
            float2 wh = *(float2*)&WSh[ei * 36 + ej2];
            float2 r;
            r.x = uu.x - wl.x - wh.x;
            r.y = uu.y - wl.y - wh.y;
            *(float2*)&UADJ[ei * 36 + ej2] = r;
        }
        __syncthreads();

        // ---- prefetch next chunk's W/Q tiles + usl/att (Wt/Qt now dead) ----
        if (ch + 1 < NCH) {
            const size_t nbase = bh_base + (size_t)(ch + 1) * CCH * DKV;
            const float4* w4 = (const float4*)(g_w + nbase);
            const float4* q4 = (const float4*)(g_qn + nbase);
#pragma unroll
            for (int r = 0; r < 4; r++) {
                int f   = t + r * 512;
                int row = f >> 6, c4 = f & 63;
                cpa16(&Wt[row * P2S + c4 * 4], &w4[f]);
                cpa16(&Qt[row * P2S + c4 * 4], &q4[f]);
            }
            if (t < 256) {
                int li = t >> 3, lj4 = (t & 7) * 4;
                cpa16(&UslN[li * 36 + lj4],
                      &g_u[nbase + (size_t)li * DKV + jb * JBW + lj4]);
                cpa16(&ATTN[li * 36 + lj4],
                      &g_att[att_base + (size_t)(ch + 1) * 1024 + li * 32 + lj4]);
            }
            cpa_commit();
        }

        // ---- GEMM C: S += k^T @ UADJ  (register-resident RMW) ----
        {
            float* srow = &St[jj * 256];
#pragma unroll 4
            for (int i = 0; i < CCH; i++) {
                unsigned long long us = splat2(UADJ[i * 36 + jj]);
                const ulonglong2* kr = (const ulonglong2*)&Kt[i * P2S + dgh * 16];
#pragma unroll
                for (int m = 0; m < 4; m++) {
                    ulonglong2 kv = kr[m];
                    sa[m].x = ffma2(kv.x, us, sa[m].x);
                    sa[m].y = ffma2(kv.y, us, sa[m].y);
                }
            }
#pragma unroll
            for (int m = 0; m < 4; m++) {
                int u = (dgh * 4 + m) ^ keyC;
                *(ulonglong2*)&srow[u << 2] = sa[m];
            }
        }
        __syncthreads();

        // ---- prefetch next chunk's K tile (Kt now dead) ----
        if (ch + 1 < NCH) {
            const size_t nbase = bh_base + (size_t)(ch + 1) * CCH * DKV;
            const float4* k4 = (const float4*)(g_kn + nbase);
#pragma unroll
            for (int r = 0; r < 4; r++) {
                int f   = t + r * 512;
                int row = f >> 6, c4 = f & 63;
                cpa16(&Kt[row * P2S + c4 * 4], &k4[f]);
            }
            cpa_commit();
        }

        // ---- O = QS + att @ UADJ ; write to global (512 threads, float2) ----
        {
            float2 ql = *(float2*)&QSl[ei * 36 + ej2];
            float2 qh = *(float2*)&QSh[ei * 36 + ej2];
            float2 o;
            o.x = ql.x + qh.x;
            o.y = ql.y + qh.y;
#pragma unroll 8
            for (int ii = 0; ii < CCH; ii++) {
                float a = ATTs[ei * 36 + ii];   // zero above diag
                float2 ub = *(float2*)&UADJ[ii * 36 + ej2];
                o.x += a * ub.x;
                o.y += a * ub.y;
            }
            *(float2*)&out[((size_t)bh * LSEQ + (size_t)ch * CCH + ei) * DKV +
                           jb * JBW + ej2] = o;
        }
        // no trailing barrier: loop-top wait + __syncthreads orders everything
    }

    // ---- final state S (second tuple element) ----
    if (write_state) {
        __syncthreads();
        const size_t soff = OUT_ELEMS;
#pragma unroll 4
        for (int m = 0; m < 16; m++) {
            int d  = dgh * 16 + m;
            int u  = (dgh * 4 + (m >> 2)) ^ keyC;
            float val = St[jj * 256 + (u << 2) + (m & 3)];
            out[soff + ((size_t)bh * DKV + d) * DKV + jb * JBW + jj] = val;
        }
    }
}

// ============================================================================

#define SM1_BYTES ((32 * P1S * 3 + 32 * 36 + 512 + 32 + 64) * sizeof(float))
#define SM2_BYTES ((32 * P2S * 3 + 32 * 256 + 9 * 32 * 36) * sizeof(float))

extern "C" void kernel_launch(void* const* d_in, const int* in_sizes, int n_in,
                              void* d_out, int out_size)
{
    const float* q    = (const float*)d_in[0];
    const float* k    = (const float*)d_in[1];
    const float* v    = (const float*)d_in[2];
    const float* beta = (const float*)d_in[3];
    float* out = (float*)d_out;

    cudaFuncSetAttribute(phase1, cudaFuncAttributeMaxDynamicSharedMemorySize, SM1_BYTES);
    cudaFuncSetAttribute(phase2, cudaFuncAttributeMaxDynamicSharedMemorySize, SM2_BYTES);

    phase1<<<dim3(NCH, BHT), 256, SM1_BYTES>>>(q, k, v, beta);

    int ws = ((size_t)out_size >= OUT_ELEMS + STATE_ELEMS) ? 1 : 0;
    phase2<<<dim3(NJB, BHT), 512, SM2_BYTES>>>(out, ws);
}